// round 15
// baseline (speedup 1.0000x reference)
#include <cuda_runtime.h>

#define TT 512
#define BB 256
#define II 64
#define NN 512
#define NB (BB*NN)
#define NBLK 144
#define NGRP 12

__device__ __align__(256) float g_Wc0[576 * NN];
__device__ __align__(256) float g_Wc1[1088 * NN];
__device__ __align__(256) float g_Wc2[1088 * NN];
__device__ __align__(256) float g_bc[3 * NN];
__device__ __align__(256) float g_S[2][3][NB];
__device__ __align__(256) float g_P[NBLK * 16384];
__device__ __align__(256) unsigned g_c1[NGRP * 32];
__device__ __align__(256) unsigned g_cm[32];
__device__ __align__(256) unsigned g_gen[32];
__device__ __align__(256) unsigned g_tc[24 * 32];

__device__ __forceinline__ unsigned long long bcast2(float x) {
    unsigned long long r;
    asm("mov.b64 %0,{%1,%1};" : "=l"(r) : "f"(x));
    return r;
}
__device__ __forceinline__ void fma2(unsigned long long& c, unsigned long long a,
                                     unsigned long long b) {
    asm("fma.rn.f32x2 %0,%1,%2,%0;" : "+l"(c) : "l"(a), "l"(b));
}
__device__ __forceinline__ float2 upk(unsigned long long v) {
    float2 f;
    asm("mov.b64 {%0,%1},%2;" : "=f"(f.x), "=f"(f.y) : "l"(v));
    return f;
}
__device__ __forceinline__ void cpa16(float* s, const float* g) {
    unsigned ss = (unsigned)__cvta_generic_to_shared(s);
    asm volatile("cp.async.cg.shared.global [%0],[%1],16;\n" ::"r"(ss), "l"(g));
}
__device__ __forceinline__ unsigned ldacq(const unsigned* p) {
    unsigned v;
    asm volatile("ld.acquire.gpu.b32 %0,[%1];" : "=r"(v) : "l"(p) : "memory");
    return v;
}
#define SPIN_GE(addr, tgt) do { while ((int)ldacq(addr) < (int)(tgt)) {} } while (0)

// Tree barrier: 12 blocks -> 12 group counters -> 1 master.
__device__ __forceinline__ void gridbar(unsigned& gen, int grp) {
    __threadfence();
    __syncthreads();
    if (threadIdx.x == 0) {
        unsigned g = gen;
        if (atomicAdd(&g_c1[grp * 32], 1u) == 11u) {
            atomicExch(&g_c1[grp * 32], 0u);
            if (atomicAdd(&g_cm[0], 1u) == NGRP - 1u) {
                atomicExch(&g_cm[0], 0u);
                __threadfence();
                asm volatile("st.release.gpu.b32 [%0],%1;" ::"l"(g_gen), "r"(g + 1u) : "memory");
            } else {
                while (ldacq(g_gen) == g) {}
            }
        } else {
            while (ldacq(g_gen) == g) {}
        }
    }
    gen++;
    __syncthreads();
}

__global__ void __launch_bounds__(256, 1) persist_kernel(
    const float* __restrict__ data, const float* __restrict__ h0,
    const float* __restrict__ Win, const float* __restrict__ b_in,
    const float* __restrict__ Whh, const float* __restrict__ b_hh,
    const float* __restrict__ Whi, const float* __restrict__ b_hi,
    const float* __restrict__ Wfc, const float* __restrict__ bfc,
    float* __restrict__ out) {
    extern __shared__ float sm[];
    float* Asb[2] = {sm, sm + 4608};             // 128 rows x stride 36
    float* Bsb[2] = {sm + 9216, sm + 13312};     // 32 k x 128 cols

    const int tid = threadIdx.x;
    const int jid = blockIdx.x;
    const int grp = jid % NGRP;
    unsigned gen = 0;
    if (tid == 0) gen = *(volatile unsigned*)g_gen;

    // ---- prep ----
    {
        int gt = jid * 256 + tid;
        const int gs = NBLK * 256;
        for (int i = gt; i < 576 * NN; i += gs) {
            int k = i >> 9, n = i & 511;
            g_Wc0[i] = (k < 512) ? ((k == n) ? 0.f : Whh[k * 512 + n])
                                 : Win[(k - 512) * 512 + n];
        }
        for (int i = gt; i < 1088 * NN; i += gs) {
            int k = i >> 9, n = i & 511;
            float v;
            if (k < 512)       v = (k == n) ? 0.f : Whh[(512 + k) * 512 + n];
            else if (k < 1024) v = Whi[(k - 512) * 512 + n];
            else               v = Win[(k - 1024) * 512 + n];
            g_Wc1[i] = v;
        }
        for (int i = gt; i < 1088 * NN; i += gs) {
            int k = i >> 9, n = i & 511;
            float v;
            if (k < 512)       v = (k == n) ? 0.f : Whh[(1024 + k) * 512 + n];
            else if (k < 1024) v = Whi[(512 + (k - 512)) * 512 + n];
            else               v = Win[(k - 1024) * 512 + n];
            g_Wc2[i] = v;
        }
        for (int i = gt; i < 3 * NN; i += gs) {
            int l = i >> 9, n = i & 511;
            float v = b_hh[i] + b_in[n];
            if (l > 0) v += b_hi[(l - 1) * 512 + n];
            g_bc[i] = v;
        }
        for (int i = gt; i < 3 * NB; i += gs) {
            float v = h0[i];
            __stcg(&(&g_S[0][0][0])[i], v);
            __stcg(&(&g_S[1][0][0])[i], v);
        }
        for (int i = gt; i < 24 * 32; i += gs) g_tc[i] = 0u;
    }
    gridbar(gen, grp);

    // ---- job decode ----
    // heavy jid<96: l=1,2; 8 tiles [128x128] x 6 K-splits (chunks 6,6,6,6,5,5)
    // light jid>=96: l=0;  8 tiles x 6 K-splits (3 chunks each)
    int l, tile, k0, nck, s, tc;
    const int nsp = 6;
    if (jid < 96) {
        l = 1 + jid / 48;
        int r = jid % 48;
        tile = r / 6; s = r % 6;
        k0 = (s < 4) ? s * 192 : 768 + (s - 4) * 160;
        nck = (s < 4) ? 6 : 5;
        tc = (l - 1) * 8 + tile;
    } else {
        int r = jid - 96;
        l = 0; tile = r / 6; s = r % 6;
        k0 = s * 96; nck = 3;
        tc = 16 + tile;
    }
    const int row0 = (tile >> 2) * 128, col0 = (tile & 3) * 128;
    const float* Wc = (l == 0) ? g_Wc0 : ((l == 1) ? g_Wc1 : g_Wc2);
    const int dbase = l ? 1024 : 512;
    const int tx = tid & 15, ty = tid >> 4;     // 16 col-groups x 16 row-groups
    const int base = jid - s;
    const int c4a = (s * 4096) / nsp, c4b = ((s + 1) * 4096) / nsp;

    auto loadB = [&](int ci, int buf) {
        const float* wsrc = Wc + (size_t)(k0 + ci * 32) * NN + col0;
        float* Bd = Bsb[buf];
#pragma unroll
        for (int i = 0; i < 4; i++) {
            int u = i * 256 + tid;
            int r = u >> 5, q = (u & 31) * 4;
            cpa16(&Bd[r * 128 + q], wsrc + (size_t)r * NN + q);
        }
    };

    if (l == 0) { loadB(0, 0); asm volatile("cp.async.commit_group;\n"); }

    for (int kk = 0; kk < TT + 2; kk++) {
        const int cur = kk & 1, prev = cur ^ 1;
        const int t = kk - l;
        if (t >= 0 && t < TT) {
            auto loadA = [&](int ci, int buf) {
                int kabs = k0 + ci * 32;
                const float* src;
                int sA;
                if (kabs < 512)                { src = &g_S[prev][l][kabs];           sA = NN; }
                else if (l > 0 && kabs < 1024) { src = &g_S[prev][l - 1][kabs - 512]; sA = NN; }
                else { src = data + (size_t)t * (BB * II) + (kabs - dbase);           sA = II; }
                src += (size_t)row0 * sA;
                float* Ad = Asb[buf];
#pragma unroll
                for (int i = 0; i < 4; i++) {
                    int u = i * 256 + tid;
                    int r = u >> 3, q = (u & 7) * 4;
                    cpa16(&Ad[r * 36 + q], src + (size_t)r * sA + q);
                }
            };

            unsigned long long acc[8][4];
#pragma unroll
            for (int m = 0; m < 8; m++)
#pragma unroll
                for (int j = 0; j < 4; j++) acc[m][j] = 0ull;

            loadA(0, 0);
            asm volatile("cp.async.commit_group;\n");
            for (int ci = 0; ci < nck; ci++) {
                int buf = ci & 1;
                if (ci + 1 < nck) {
                    loadA(ci + 1, buf ^ 1);
                    loadB(ci + 1, buf ^ 1);
                    asm volatile("cp.async.commit_group;\n");
                    asm volatile("cp.async.wait_group 1;\n");
                } else {
                    asm volatile("cp.async.wait_group 0;\n");
                }
                __syncthreads();
                const float* A = Asb[buf];
                const float* Bp = Bsb[buf];
#pragma unroll 2
                for (int k = 0; k < 32; k += 2) {
                    const float* Br0 = &Bp[k * 128 + tx * 2];
                    const float* Br1 = &Bp[(k + 1) * 128 + tx * 2];
                    unsigned long long B00 = *(const unsigned long long*)&Br0[0];
                    unsigned long long B01 = *(const unsigned long long*)&Br0[32];
                    unsigned long long B02 = *(const unsigned long long*)&Br0[64];
                    unsigned long long B03 = *(const unsigned long long*)&Br0[96];
                    unsigned long long B10 = *(const unsigned long long*)&Br1[0];
                    unsigned long long B11 = *(const unsigned long long*)&Br1[32];
                    unsigned long long B12 = *(const unsigned long long*)&Br1[64];
                    unsigned long long B13 = *(const unsigned long long*)&Br1[96];
#pragma unroll
                    for (int m = 0; m < 8; m++) {
                        float2 a = *(const float2*)&A[(ty + 16 * m) * 36 + k];
                        unsigned long long a0 = bcast2(a.x), a1 = bcast2(a.y);
                        fma2(acc[m][0], a0, B00);
                        fma2(acc[m][1], a0, B01);
                        fma2(acc[m][2], a0, B02);
                        fma2(acc[m][3], a0, B03);
                        fma2(acc[m][0], a1, B10);
                        fma2(acc[m][1], a1, B11);
                        fma2(acc[m][2], a1, B12);
                        fma2(acc[m][3], a1, B13);
                    }
                }
                __syncthreads();
            }

            // publish partial (128x128 tile)
            {
                float* P = &g_P[(size_t)jid * 16384];
#pragma unroll
                for (int m = 0; m < 8; m++)
#pragma unroll
                    for (int j = 0; j < 4; j++) {
                        float2 v = upk(acc[m][j]);
                        __stcg((float2*)&P[(ty + 16 * m) * 128 + j * 32 + tx * 2], v);
                    }
            }
            __threadfence();
            __syncthreads();
            if (tid == 0) {
                atomicAdd(&g_tc[tc * 32], 1u);
                SPIN_GE(&g_tc[tc * 32], nsp * (t + 1));
            }
            __syncthreads();

            // distributed combine: this split's float4 slice [c4a, c4b)
            {
                const float* hold = g_S[prev][l];
                float* dst = g_S[cur][l];
                const float* bias = &g_bc[l * NN];
                for (int i4 = c4a + tid; i4 < c4b; i4 += 256) {
                    float4 sv = __ldcg((const float4*)&g_P[(size_t)base * 16384] + i4);
                    for (int sp = 1; sp < nsp; sp++) {
                        float4 p = __ldcg((const float4*)&g_P[(size_t)(base + sp) * 16384] + i4);
                        sv.x += p.x; sv.y += p.y; sv.z += p.z; sv.w += p.w;
                    }
                    int e = i4 * 4;
                    int gr = row0 + (e >> 7), gc = col0 + (e & 127);
                    float4 h = __ldcg((const float4*)&hold[gr * NN + gc]);
                    float4 b = *(const float4*)&bias[gc];
                    float4 o;
                    o.x = 0.5f * h.x + 0.5f * (sv.x + b.x);
                    o.y = 0.5f * h.y + 0.5f * (sv.y + b.y);
                    o.z = 0.5f * h.z + 0.5f * (sv.z + b.z);
                    o.w = 0.5f * h.w + 0.5f * (sv.w + b.w);
                    o.x = (o.x > 0.f) ? o.x : 0.01f * o.x;
                    o.y = (o.y > 0.f) ? o.y : 0.01f * o.y;
                    o.z = (o.z > 0.f) ? o.z : 0.01f * o.z;
                    o.w = (o.w > 0.f) ? o.w : 0.01f * o.w;
                    __stcg((float4*)&dst[gr * NN + gc], o);
                }
            }
        }
        // prefetch next tick's B0 during the barrier (weights are tick-invariant)
        int tn = kk + 1 - l;
        if (tn >= 0 && tn < TT) {
            loadB(0, 0);
            asm volatile("cp.async.commit_group;\n");
        }
        gridbar(gen, grp);
    }

    // ---- readout ----
    {
        int warp0 = jid * 8 + (tid >> 5);
        int lane = tid & 31;
        for (int gw = warp0; gw < BB * 10; gw += NBLK * 8) {
            int b = gw / 10, c = gw % 10;
            const float* h = &g_S[1][2][b * NN];
            float sv = 0.f;
            for (int k = lane; k < NN; k += 32)
                sv += __ldcg(&h[k]) * Wfc[k * 10 + c];
#pragma unroll
            for (int o = 16; o; o >>= 1) sv += __shfl_down_sync(0xffffffffu, sv, o);
            if (lane == 0) out[b * 10 + c] = sv + bfc[c];
        }
    }
}

extern "C" void kernel_launch(void* const* d_in, const int* in_sizes, int n_in,
                              void* d_out, int out_size) {
    const float* data = (const float*)d_in[0];
    const float* h0   = (const float*)d_in[1];
    const float* Win  = (const float*)d_in[2];
    const float* b_in = (const float*)d_in[3];
    const float* Whh  = (const float*)d_in[4];
    const float* b_hh = (const float*)d_in[5];
    const float* Whi  = (const float*)d_in[6];
    const float* b_hi = (const float*)d_in[7];
    const float* Wfc  = (const float*)d_in[8];
    const float* b_fc = (const float*)d_in[9];
    float* out = (float*)d_out;

    cudaFuncSetAttribute(persist_kernel, cudaFuncAttributeMaxDynamicSharedMemorySize, 69632);
    persist_kernel<<<NBLK, 256, 69632>>>(data, h0, Win, b_in, Whh, b_hh, Whi, b_hi,
                                         Wfc, b_fc, out);
}

// round 16
// speedup vs baseline: 1.0833x; 1.0833x over previous
#include <cuda_runtime.h>

#define TT 512
#define BB 256
#define II 64
#define NN 512
#define NB (BB*NN)
#define NBLK 144
#define NGRP 12

__device__ __align__(256) float g_Wc0[576 * NN];
__device__ __align__(256) float g_Wc1[1088 * NN];
__device__ __align__(256) float g_Wc2[1088 * NN];
__device__ __align__(256) float g_bc[3 * NN];
__device__ __align__(256) float g_S[2][3][NB];
__device__ __align__(256) float g_P[NBLK * 16384];
__device__ __align__(256) unsigned g_c1[NGRP * 32];
__device__ __align__(256) unsigned g_cm[32];
__device__ __align__(256) unsigned g_gen[32];
__device__ __align__(256) unsigned g_tc[24 * 32];

__device__ __forceinline__ unsigned long long bcast2(float x) {
    unsigned long long r;
    asm("mov.b64 %0,{%1,%1};" : "=l"(r) : "f"(x));
    return r;
}
__device__ __forceinline__ void fma2(unsigned long long& c, unsigned long long a,
                                     unsigned long long b) {
    asm("fma.rn.f32x2 %0,%1,%2,%0;" : "+l"(c) : "l"(a), "l"(b));
}
__device__ __forceinline__ float2 upk(unsigned long long v) {
    float2 f;
    asm("mov.b64 {%0,%1},%2;" : "=f"(f.x), "=f"(f.y) : "l"(v));
    return f;
}
__device__ __forceinline__ void cpa16(float* s, const float* g) {
    unsigned ss = (unsigned)__cvta_generic_to_shared(s);
    asm volatile("cp.async.cg.shared.global [%0],[%1],16;\n" ::"r"(ss), "l"(g));
}
__device__ __forceinline__ unsigned ldacq(const unsigned* p) {
    unsigned v;
    asm volatile("ld.acquire.gpu.b32 %0,[%1];" : "=r"(v) : "l"(p) : "memory");
    return v;
}
#define SPIN_GE(addr, tgt) do { while ((int)ldacq(addr) < (int)(tgt)) {} } while (0)

// Tree barrier: 12 blocks -> 12 group counters -> 1 master.
__device__ __forceinline__ void gridbar(unsigned& gen, int grp) {
    __threadfence();
    __syncthreads();
    if (threadIdx.x == 0) {
        unsigned g = gen;
        if (atomicAdd(&g_c1[grp * 32], 1u) == 11u) {
            atomicExch(&g_c1[grp * 32], 0u);
            if (atomicAdd(&g_cm[0], 1u) == NGRP - 1u) {
                atomicExch(&g_cm[0], 0u);
                __threadfence();
                asm volatile("st.release.gpu.b32 [%0],%1;" ::"l"(g_gen), "r"(g + 1u) : "memory");
            } else {
                while (ldacq(g_gen) == g) {}
            }
        } else {
            while (ldacq(g_gen) == g) {}
        }
    }
    gen++;
    __syncthreads();
}

__global__ void __launch_bounds__(256, 1) persist_kernel(
    const float* __restrict__ data, const float* __restrict__ h0,
    const float* __restrict__ Win, const float* __restrict__ b_in,
    const float* __restrict__ Whh, const float* __restrict__ b_hh,
    const float* __restrict__ Whi, const float* __restrict__ b_hi,
    const float* __restrict__ Wfc, const float* __restrict__ bfc,
    float* __restrict__ out) {
    extern __shared__ float sm[];
    float* Asb[2] = {sm, sm + 4608};             // 128 rows x stride 36
    float* Bsb[2] = {sm + 9216, sm + 13312};     // 32 k x 128 cols

    const int tid = threadIdx.x;
    const int jid = blockIdx.x;
    const int grp = jid % NGRP;
    unsigned gen = 0;
    if (tid == 0) gen = *(volatile unsigned*)g_gen;

    // ---- prep ----
    {
        int gt = jid * 256 + tid;
        const int gs = NBLK * 256;
        for (int i = gt; i < 576 * NN; i += gs) {
            int k = i >> 9, n = i & 511;
            g_Wc0[i] = (k < 512) ? ((k == n) ? 0.f : Whh[k * 512 + n])
                                 : Win[(k - 512) * 512 + n];
        }
        for (int i = gt; i < 1088 * NN; i += gs) {
            int k = i >> 9, n = i & 511;
            float v;
            if (k < 512)       v = (k == n) ? 0.f : Whh[(512 + k) * 512 + n];
            else if (k < 1024) v = Whi[(k - 512) * 512 + n];
            else               v = Win[(k - 1024) * 512 + n];
            g_Wc1[i] = v;
        }
        for (int i = gt; i < 1088 * NN; i += gs) {
            int k = i >> 9, n = i & 511;
            float v;
            if (k < 512)       v = (k == n) ? 0.f : Whh[(1024 + k) * 512 + n];
            else if (k < 1024) v = Whi[(512 + (k - 512)) * 512 + n];
            else               v = Win[(k - 1024) * 512 + n];
            g_Wc2[i] = v;
        }
        for (int i = gt; i < 3 * NN; i += gs) {
            int l = i >> 9, n = i & 511;
            float v = b_hh[i] + b_in[n];
            if (l > 0) v += b_hi[(l - 1) * 512 + n];
            g_bc[i] = v;
        }
        for (int i = gt; i < 3 * NB; i += gs) {
            float v = h0[i];
            __stcg(&(&g_S[0][0][0])[i], v);
            __stcg(&(&g_S[1][0][0])[i], v);
        }
        for (int i = gt; i < 24 * 32; i += gs) g_tc[i] = 0u;
    }
    gridbar(gen, grp);

    // ---- job decode ----
    // heavy jid<112: l=1,2; 8 tiles [128x128] x 7 K-splits (chunks 5,5,5,5,5,5,4)
    // light jid>=112: l=0;  8 tiles x 4 K-splits (chunks 5,5,4,4)
    int l, tile, k0, nck, s, tc, nsp;
    if (jid < 112) {
        l = 1 + jid / 56;
        int r = jid % 56;
        tile = r / 7; s = r % 7;
        k0 = s * 160; nck = (s < 6) ? 5 : 4;
        nsp = 7; tc = (l - 1) * 8 + tile;
    } else {
        int r = jid - 112;
        l = 0; tile = r >> 2; s = r & 3;
        k0 = (s < 2) ? s * 160 : 320 + (s - 2) * 128;
        nck = (s < 2) ? 5 : 4;
        nsp = 4; tc = 16 + tile;
    }
    const int row0 = (tile >> 2) * 128, col0 = (tile & 3) * 128;
    const float* Wc = (l == 0) ? g_Wc0 : ((l == 1) ? g_Wc1 : g_Wc2);
    const int dbase = l ? 1024 : 512;
    const int tx = tid & 15, ty = tid >> 4;     // 16 col-groups x 16 row-groups
    const int base = jid - s;
    const int c4a = (s * 4096) / nsp, c4b = ((s + 1) * 4096) / nsp;

    auto loadB = [&](int ci, int buf) {
        const float* wsrc = Wc + (size_t)(k0 + ci * 32) * NN + col0;
        float* Bd = Bsb[buf];
#pragma unroll
        for (int i = 0; i < 4; i++) {
            int u = i * 256 + tid;
            int r = u >> 5, q = (u & 31) * 4;
            cpa16(&Bd[r * 128 + q], wsrc + (size_t)r * NN + q);
        }
    };

    if (l == 0) { loadB(0, 0); asm volatile("cp.async.commit_group;\n"); }

    for (int kk = 0; kk < TT + 2; kk++) {
        const int cur = kk & 1, prev = cur ^ 1;
        const int t = kk - l;
        if (t >= 0 && t < TT) {
            auto loadA = [&](int ci, int buf) {
                int kabs = k0 + ci * 32;
                const float* src;
                int sA;
                if (kabs < 512)                { src = &g_S[prev][l][kabs];           sA = NN; }
                else if (l > 0 && kabs < 1024) { src = &g_S[prev][l - 1][kabs - 512]; sA = NN; }
                else { src = data + (size_t)t * (BB * II) + (kabs - dbase);           sA = II; }
                src += (size_t)row0 * sA;
                float* Ad = Asb[buf];
#pragma unroll
                for (int i = 0; i < 4; i++) {
                    int u = i * 256 + tid;
                    int r = u >> 3, q = (u & 7) * 4;
                    cpa16(&Ad[r * 36 + q], src + (size_t)r * sA + q);
                }
            };

            unsigned long long acc[8][4];
#pragma unroll
            for (int m = 0; m < 8; m++)
#pragma unroll
                for (int j = 0; j < 4; j++) acc[m][j] = 0ull;

            loadA(0, 0);
            asm volatile("cp.async.commit_group;\n");
            for (int ci = 0; ci < nck; ci++) {
                int buf = ci & 1;
                if (ci + 1 < nck) {
                    loadA(ci + 1, buf ^ 1);
                    loadB(ci + 1, buf ^ 1);
                    asm volatile("cp.async.commit_group;\n");
                    asm volatile("cp.async.wait_group 1;\n");
                } else {
                    asm volatile("cp.async.wait_group 0;\n");
                }
                __syncthreads();
                const float* A = Asb[buf];
                const float* Bp = Bsb[buf];
#pragma unroll 2
                for (int k = 0; k < 32; k += 2) {
                    const float* Br0 = &Bp[k * 128 + tx * 2];
                    const float* Br1 = &Bp[(k + 1) * 128 + tx * 2];
                    unsigned long long B00 = *(const unsigned long long*)&Br0[0];
                    unsigned long long B01 = *(const unsigned long long*)&Br0[32];
                    unsigned long long B02 = *(const unsigned long long*)&Br0[64];
                    unsigned long long B03 = *(const unsigned long long*)&Br0[96];
                    unsigned long long B10 = *(const unsigned long long*)&Br1[0];
                    unsigned long long B11 = *(const unsigned long long*)&Br1[32];
                    unsigned long long B12 = *(const unsigned long long*)&Br1[64];
                    unsigned long long B13 = *(const unsigned long long*)&Br1[96];
#pragma unroll
                    for (int m = 0; m < 8; m++) {
                        float2 a = *(const float2*)&A[(ty + 16 * m) * 36 + k];
                        unsigned long long a0 = bcast2(a.x), a1 = bcast2(a.y);
                        fma2(acc[m][0], a0, B00);
                        fma2(acc[m][1], a0, B01);
                        fma2(acc[m][2], a0, B02);
                        fma2(acc[m][3], a0, B03);
                        fma2(acc[m][0], a1, B10);
                        fma2(acc[m][1], a1, B11);
                        fma2(acc[m][2], a1, B12);
                        fma2(acc[m][3], a1, B13);
                    }
                }
                __syncthreads();
            }

            // publish partial (128x128 tile)
            {
                float* P = &g_P[(size_t)jid * 16384];
#pragma unroll
                for (int m = 0; m < 8; m++)
#pragma unroll
                    for (int j = 0; j < 4; j++) {
                        float2 v = upk(acc[m][j]);
                        __stcg((float2*)&P[(ty + 16 * m) * 128 + j * 32 + tx * 2], v);
                    }
            }
            __threadfence();
            __syncthreads();
            if (tid == 0) {
                atomicAdd(&g_tc[tc * 32], 1u);
                SPIN_GE(&g_tc[tc * 32], nsp * (t + 1));
            }
            __syncthreads();

            // distributed combine: this split's float4 slice [c4a, c4b)
            {
                const float* hold = g_S[prev][l];
                float* dst = g_S[cur][l];
                const float* bias = &g_bc[l * NN];
                for (int i4 = c4a + tid; i4 < c4b; i4 += 256) {
                    float4 sv = __ldcg((const float4*)&g_P[(size_t)base * 16384] + i4);
                    for (int sp = 1; sp < nsp; sp++) {
                        float4 p = __ldcg((const float4*)&g_P[(size_t)(base + sp) * 16384] + i4);
                        sv.x += p.x; sv.y += p.y; sv.z += p.z; sv.w += p.w;
                    }
                    int e = i4 * 4;
                    int gr = row0 + (e >> 7), gc = col0 + (e & 127);
                    float4 h = __ldcg((const float4*)&hold[gr * NN + gc]);
                    float4 b = *(const float4*)&bias[gc];
                    float4 o;
                    o.x = 0.5f * h.x + 0.5f * (sv.x + b.x);
                    o.y = 0.5f * h.y + 0.5f * (sv.y + b.y);
                    o.z = 0.5f * h.z + 0.5f * (sv.z + b.z);
                    o.w = 0.5f * h.w + 0.5f * (sv.w + b.w);
                    o.x = (o.x > 0.f) ? o.x : 0.01f * o.x;
                    o.y = (o.y > 0.f) ? o.y : 0.01f * o.y;
                    o.z = (o.z > 0.f) ? o.z : 0.01f * o.z;
                    o.w = (o.w > 0.f) ? o.w : 0.01f * o.w;
                    __stcg((float4*)&dst[gr * NN + gc], o);
                }
            }
        }
        // prefetch next tick's B0 during the barrier (weights are tick-invariant)
        int tn = kk + 1 - l;
        if (tn >= 0 && tn < TT) {
            loadB(0, 0);
            asm volatile("cp.async.commit_group;\n");
        }
        gridbar(gen, grp);
    }

    // ---- readout ----
    {
        int warp0 = jid * 8 + (tid >> 5);
        int lane = tid & 31;
        for (int gw = warp0; gw < BB * 10; gw += NBLK * 8) {
            int b = gw / 10, c = gw % 10;
            const float* h = &g_S[1][2][b * NN];
            float sv = 0.f;
            for (int k = lane; k < NN; k += 32)
                sv += __ldcg(&h[k]) * Wfc[k * 10 + c];
#pragma unroll
            for (int o = 16; o; o >>= 1) sv += __shfl_down_sync(0xffffffffu, sv, o);
            if (lane == 0) out[b * 10 + c] = sv + bfc[c];
        }
    }
}

extern "C" void kernel_launch(void* const* d_in, const int* in_sizes, int n_in,
                              void* d_out, int out_size) {
    const float* data = (const float*)d_in[0];
    const float* h0   = (const float*)d_in[1];
    const float* Win  = (const float*)d_in[2];
    const float* b_in = (const float*)d_in[3];
    const float* Whh  = (const float*)d_in[4];
    const float* b_hh = (const float*)d_in[5];
    const float* Whi  = (const float*)d_in[6];
    const float* b_hi = (const float*)d_in[7];
    const float* Wfc  = (const float*)d_in[8];
    const float* b_fc = (const float*)d_in[9];
    float* out = (float*)d_out;

    cudaFuncSetAttribute(persist_kernel, cudaFuncAttributeMaxDynamicSharedMemorySize, 69632);
    persist_kernel<<<NBLK, 256, 69632>>>(data, h0, Win, b_in, Whh, b_hh, Whi, b_hi,
                                         Wfc, b_fc, out);
}